// round 4
// baseline (speedup 1.0000x reference)
#include <cuda_runtime.h>
#include <cuda_bf16.h>
#include <math.h>

// Problem constants
#define BATCH 256
#define HID   768
#define G4    3072          // 4 * HID
#define TLEN  100
#define OUTD  72
#define SRCL  16
#define BH    (BATCH * HID) // 196608

// -------- device scratch (allocation-free: __device__ globals) --------
static __device__ float g_W0pack[1536 * 3072]; // packed [Wih|Whh] : [k][jt*96 + g*24 + jj]
static __device__ float g_Wcpack[768 * 3072];  // packed (Wih+Whh) : same col layout
static __device__ float g_A0[BATCH * 1536];    // [x0 | h0]
static __device__ float g_C[BATCH * HID];      // cell state
static __device__ float g_H[TLEN * BATCH * HID]; // h history (GEMM A for next step)
static __device__ float g_bias[G4];            // b_ih + b_hh

// -------- f32x2 packed-math helpers (B300: 2x fp32 throughput) --------
__device__ __forceinline__ unsigned long long pack2(float x, float y) {
    unsigned long long r;
    asm("mov.b64 %0, {%1, %2};" : "=l"(r) : "f"(x), "f"(y));
    return r;
}
__device__ __forceinline__ void unpack2(unsigned long long v, float& x, float& y) {
    asm("mov.b64 {%0, %1}, %2;" : "=f"(x), "=f"(y) : "l"(v));
}
__device__ __forceinline__ void fma2(unsigned long long& d,
                                     unsigned long long a,
                                     unsigned long long b) {
    asm("fma.rn.f32x2 %0, %1, %2, %0;" : "+l"(d) : "l"(a), "l"(b));
}

__device__ __forceinline__ float sigmoidf_(float x) {
    return 1.0f / (1.0f + expf(-x));
}

// ====================================================================
// Prep 1: pack [W_ih ; W_hh] -> g_W0pack[k][col], col = jt*96 + g*24 + jj
// ====================================================================
__global__ void prepW0(const float* __restrict__ Wih, const float* __restrict__ Whh) {
    const int stride = gridDim.x * blockDim.x;
    for (int idx = blockIdx.x * blockDim.x + threadIdx.x; idx < 1536 * 3072; idx += stride) {
        int k   = idx / 3072;
        int col = idx - k * 3072;
        int jt  = col / 96;
        int r   = col - jt * 96;
        int g   = r / 24;
        int jj  = r - g * 24;
        int row = g * HID + jt * 24 + jj; // row in the 4H x H weight
        float v = (k < HID) ? Wih[row * HID + k] : Whh[row * HID + (k - HID)];
        g_W0pack[idx] = v;
    }
}

// ====================================================================
// Prep 2: Wcomb pack (from W0pack, coalesced), A0, C init, bias
// ====================================================================
__global__ void prepRest(const float* __restrict__ src, const float* __restrict__ h0,
                         const float* __restrict__ c0, const float* __restrict__ bih,
                         const float* __restrict__ bhh) {
    const int stride = gridDim.x * blockDim.x;
    const int t0 = blockIdx.x * blockDim.x + threadIdx.x;

    // Wcomb[k][col] = W0pack[k][col] + W0pack[k+768][col]
    for (int idx = t0; idx < 768 * 3072; idx += stride)
        g_Wcpack[idx] = g_W0pack[idx] + g_W0pack[idx + 768 * 3072];

    // A0 = [x0 | h0], x0 = src[:, SRCL-1, :]
    for (int idx = t0; idx < BATCH * 1536; idx += stride) {
        int b = idx / 1536;
        int q = idx - b * 1536;
        g_A0[idx] = (q < HID) ? src[(b * SRCL + (SRCL - 1)) * HID + q]
                              : h0[b * HID + (q - HID)];
    }

    // C state init
    for (int idx = t0; idx < BATCH * HID; idx += stride)
        g_C[idx] = c0[idx];

    // fused bias
    for (int idx = t0; idx < G4; idx += stride)
        g_bias[idx] = bih[idx] + bhh[idx];
}

// ====================================================================
// LSTM step: gates GEMM (M=256, Npacked=3072, K=768 or 1536) + pointwise
// grid (32 jt, 4 mt), 256 threads. CTA gate tile: 64 m x (24 j x 4 gates).
// Per-thread: 4 m x 3 j-pairs x 4 gates = 12 f32x2 accumulators.
// ====================================================================
__global__ __launch_bounds__(256) void lstm_step(int t) {
    __shared__ float sA[16][68];   // [k][m], padded for STS banking + float4 LDS align
    __shared__ float sW[16][96];   // [k][packed col]
    __shared__ float sG[64][96];   // gate tile for pointwise

    const float* A;
    int lda, kTot;
    if (t == 0) { A = g_A0; lda = 1536; kTot = 1536; }
    else        { A = g_H + (size_t)(t - 1) * BH; lda = HID; kTot = HID; }
    const float* __restrict__ Wp = (t == 0) ? g_W0pack : g_Wcpack;
    float* __restrict__ hOut = g_H + (size_t)t * BH;

    const int tid = threadIdx.x;
    const int jt  = blockIdx.x;
    const int m0  = blockIdx.y * 64;
    const int tm  = tid >> 4;         // 0..15  (4 m rows each)
    const int tc  = tid & 15;         // 0..15  (6 packed cols each)
    const int lr  = tid >> 2;         // 0..63  A-load row
    const int lk  = (tid & 3) * 4;    // A-load k offset (float4)

    const float* __restrict__ Wbase = Wp + jt * 96;

    // per-thread W-load coordinates (6 elements, 16k x 96c = 1536 = 6*256)
    int wk[6], wc[6];
#pragma unroll
    for (int l = 0; l < 6; l++) {
        int lin = tid + 256 * l;
        wk[l] = lin / 96;
        wc[l] = lin - wk[l] * 96;
    }

    unsigned long long acc[4][3];
#pragma unroll
    for (int mi = 0; mi < 4; mi++)
#pragma unroll
        for (int wi = 0; wi < 3; wi++) acc[mi][wi] = 0ull;

    const int nCh = kTot >> 4;

    // prefetch chunk 0
    const float* aPtr = A + (size_t)(m0 + lr) * lda + lk;
    float4 aReg = *(const float4*)aPtr;
    float wReg[6];
#pragma unroll
    for (int l = 0; l < 6; l++)
        wReg[l] = Wbase[(size_t)wk[l] * G4 + wc[l]];

    for (int ch = 0; ch < nCh; ch++) {
        // stage prefetched regs -> smem
        sA[lk + 0][lr] = aReg.x;
        sA[lk + 1][lr] = aReg.y;
        sA[lk + 2][lr] = aReg.z;
        sA[lk + 3][lr] = aReg.w;
#pragma unroll
        for (int l = 0; l < 6; l++) sW[wk[l]][wc[l]] = wReg[l];
        __syncthreads();

        // prefetch next chunk (overlap global latency with compute)
        if (ch + 1 < nCh) {
            int kc = (ch + 1) << 4;
            aReg = *(const float4*)(aPtr + kc);
#pragma unroll
            for (int l = 0; l < 6; l++)
                wReg[l] = Wbase[(size_t)(kc + wk[l]) * G4 + wc[l]];
        }

#pragma unroll
        for (int k = 0; k < 16; k++) {
            float4 a4 = *(const float4*)&sA[k][tm * 4];
            unsigned long long a2[4];
            a2[0] = pack2(a4.x, a4.x);
            a2[1] = pack2(a4.y, a4.y);
            a2[2] = pack2(a4.z, a4.z);
            a2[3] = pack2(a4.w, a4.w);
            unsigned long long w[3];
#pragma unroll
            for (int wi = 0; wi < 3; wi++)
                w[wi] = *(const unsigned long long*)&sW[k][tc * 6 + 2 * wi];
#pragma unroll
            for (int mi = 0; mi < 4; mi++)
#pragma unroll
                for (int wi = 0; wi < 3; wi++)
                    fma2(acc[mi][wi], a2[mi], w[wi]);
        }
        __syncthreads();
    }

    // gates -> smem for pointwise regrouping
#pragma unroll
    for (int mi = 0; mi < 4; mi++)
#pragma unroll
        for (int wi = 0; wi < 3; wi++)
            *(unsigned long long*)&sG[tm * 4 + mi][tc * 6 + 2 * wi] = acc[mi][wi];
    __syncthreads();

    // fused LSTM pointwise: 64 m x 24 j = 1536 elems / 256 threads = 6 each
#pragma unroll
    for (int e = 0; e < 6; e++) {
        int lin = e * 256 + tid;
        int m  = lin / 24;
        int jj = lin - m * 24;
        int gj = jt * 24 + jj;          // global hidden index
        int b  = m0 + m;
        float gi = sG[m][jj]      + g_bias[gj];
        float gf = sG[m][24 + jj] + g_bias[HID + gj];
        float gg = sG[m][48 + jj] + g_bias[2 * HID + gj];
        float go = sG[m][72 + jj] + g_bias[3 * HID + gj];
        float si = sigmoidf_(gi);
        float sf = sigmoidf_(gf);
        float so = sigmoidf_(go);
        float tg = tanhf(gg);
        int ci = b * HID + gj;
        float c = sf * g_C[ci] + si * tg;
        g_C[ci]  = c;
        hOut[ci] = so * tanhf(c);
    }
}

// ====================================================================
// Post projection: out[b][t][o] = H[t][b][:] . W_post[o][:] + b_post[o]
// grid (100 t, 4 mt), 128 threads. Thread tile: 2 m x 18 o (f32x2 over o-pairs).
// ====================================================================
__global__ __launch_bounds__(128) void post_proj(const float* __restrict__ Wpost,
                                                 const float* __restrict__ bpost,
                                                 float* __restrict__ out) {
    __shared__ float pA[16][64];  // [k][m]
    __shared__ float pW[16][72];  // [k][o]

    const int tid = threadIdx.x;
    const int t   = blockIdx.x;
    const int m0  = blockIdx.y * 64;
    const int tm  = tid >> 2;          // 0..31 -> m = 2*tm
    const int to  = tid & 3;           // 0..3  -> o base = 18*to
    const int m   = 2 * tm;
    const int ob  = 18 * to;

    const int lr = tid >> 1;           // 0..63 A-load row
    const int lk = (tid & 1) * 8;      // A-load k offset (two float4)

    const float* __restrict__ Abase = g_H + (size_t)t * BH + (size_t)m0 * HID;

    unsigned long long acc[2][9];
#pragma unroll
    for (int mi = 0; mi < 2; mi++)
#pragma unroll
        for (int oi = 0; oi < 9; oi++) acc[mi][oi] = 0ull;

    for (int kc = 0; kc < HID; kc += 16) {
        // load A tile: 16k x 64m = 1024 floats / 128 thr = 8 each
        float4 v0 = *(const float4*)&Abase[(size_t)lr * HID + kc + lk];
        float4 v1 = *(const float4*)&Abase[(size_t)lr * HID + kc + lk + 4];
        pA[lk + 0][lr] = v0.x; pA[lk + 1][lr] = v0.y;
        pA[lk + 2][lr] = v0.z; pA[lk + 3][lr] = v0.w;
        pA[lk + 4][lr] = v1.x; pA[lk + 5][lr] = v1.y;
        pA[lk + 6][lr] = v1.z; pA[lk + 7][lr] = v1.w;
        // load W tile: 16k x 72o = 1152 / 128 = 9 each
#pragma unroll
        for (int l = 0; l < 9; l++) {
            int lin = tid + 128 * l;
            int k = lin / 72;
            int o = lin - k * 72;
            pW[k][o] = Wpost[o * HID + kc + k];
        }
        __syncthreads();

#pragma unroll
        for (int k = 0; k < 16; k++) {
            float2 av = *(const float2*)&pA[k][m];
            unsigned long long a0 = pack2(av.x, av.x);
            unsigned long long a1 = pack2(av.y, av.y);
#pragma unroll
            for (int oi = 0; oi < 9; oi++) {
                unsigned long long w = *(const unsigned long long*)&pW[k][ob + 2 * oi];
                fma2(acc[0][oi], a0, w);
                fma2(acc[1][oi], a1, w);
            }
        }
        __syncthreads();
    }

#pragma unroll
    for (int mi = 0; mi < 2; mi++) {
        int b = m0 + m + mi;
        float* orow = out + (size_t)b * (TLEN * OUTD) + t * OUTD;
#pragma unroll
        for (int oi = 0; oi < 9; oi++) {
            float x, y;
            unpack2(acc[mi][oi], x, y);
            int o = ob + 2 * oi;
            orow[o]     = x + bpost[o];
            orow[o + 1] = y + bpost[o + 1];
        }
    }
}

// ====================================================================
// kernel_launch: prep -> 100 sequential LSTM steps -> projection
// (graph-capturable: kernel launches only, no allocs/syncs)
// ====================================================================
extern "C" void kernel_launch(void* const* d_in, const int* in_sizes, int n_in,
                              void* d_out, int out_size) {
    const float* src   = (const float*)d_in[0];
    // d_in[1] = tgt (only its length T matters; unused at runtime)
    const float* h0    = (const float*)d_in[2];
    const float* c0    = (const float*)d_in[3];
    const float* Wih   = (const float*)d_in[4];
    const float* Whh   = (const float*)d_in[5];
    const float* bih   = (const float*)d_in[6];
    const float* bhh   = (const float*)d_in[7];
    const float* Wpost = (const float*)d_in[8];
    const float* bpost = (const float*)d_in[9];
    float* out = (float*)d_out;

    prepW0<<<2048, 256>>>(Wih, Whh);
    prepRest<<<2048, 256>>>(src, h0, c0, bih, bhh);

    dim3 sgrid(32, 4);
    for (int t = 0; t < TLEN; t++)
        lstm_step<<<sgrid, 256>>>(t);

    dim3 pgrid(TLEN, 4);
    post_proj<<<pgrid, 128>>>(Wpost, bpost, out);
}